// round 15
// baseline (speedup 1.0000x reference)
#include <cuda_runtime.h>
#include <cuda_fp16.h>
#include <cstdint>

#define H0 200
#define W0 304
#define H1 100
#define W1 152
#define H2 50
#define W2 76
#define HW0 (H0*W0)
#define C_TOT 768

// Fused HWC fp16 map, 16B-aligned: [H0*W0][96 octets of 8ch]
__device__ uint4 g_fused[(size_t)HW0 * (C_TOT/8)];

#define P1_PAD 65
#define P2_PAD 65

// ---------------------------------------------------------------------------
// prep0: transpose feat0 (CHW fp32) -> g_fused channels [0,256)
// ---------------------------------------------------------------------------
__global__ __launch_bounds__(256) void prep0_kernel(const float* __restrict__ f0) {
    __shared__ float tile[64][33];
    int y = blockIdx.y, xblk = blockIdx.x * 32, g = blockIdx.z;
    int warp = threadIdx.x >> 5, lane = threadIdx.x & 31;
    int x = xblk + lane;
    int c0 = g * 64;
    __half* gf = (__half*)g_fused;
    if (x < W0) {
        const float* src = f0 + (size_t)c0 * HW0 + y * W0 + x;
#pragma unroll
        for (int p = 0; p < 8; p++) {
            int cl = warp * 8 + p;
            tile[cl][lane] = __ldg(src + (size_t)cl * HW0);
        }
    }
    __syncthreads();
#pragma unroll
    for (int q = 0; q < 4; q++) {
        int px = warp * 4 + q, xg = xblk + px;
        if (xg < W0) {
            __half2 v = __floats2half2_rn(tile[2 * lane][px], tile[2 * lane + 1][px]);
            *(__half2*)(gf + (size_t)(y * W0 + xg) * C_TOT + c0 + 2 * lane) = v;
        }
    }
}

// ---------------------------------------------------------------------------
// prep1: 2x upsample feat1 -> channels [256,512). Constant-phase separable.
// ---------------------------------------------------------------------------
__global__ __launch_bounds__(256) void prep1_kernel(const float* __restrict__ f1) {
    __shared__ __half tile[2 * 64 * P1_PAD];
    int Y  = blockIdx.y;
    int xb = blockIdx.x * 64;
    int cb = blockIdx.z * 64;
    int warp = threadIdx.x >> 5, lane = threadIdx.x & 31;
    __half* gf = (__half*)g_fused;
    int j  = xb / 2 + lane;
    int xm = max(j - 1, 0), xc = min(j, W1 - 1), xp = min(j + 1, W1 - 1);
    int r0 = max(Y - 1, 0), r1 = Y, r2 = min(Y + 1, H1 - 1);
#pragma unroll
    for (int p = 0; p < 8; p++) {
        int cl = warp * 8 + p;
        const float* pl = f1 + (size_t)(cb + cl) * (H1 * W1);
        float v00 = __ldg(pl + r0 * W1 + xm), v01 = __ldg(pl + r0 * W1 + xc), v02 = __ldg(pl + r0 * W1 + xp);
        float v10 = __ldg(pl + r1 * W1 + xm), v11 = __ldg(pl + r1 * W1 + xc), v12 = __ldg(pl + r1 * W1 + xp);
        float v20 = __ldg(pl + r2 * W1 + xm), v21 = __ldg(pl + r2 * W1 + xc), v22 = __ldg(pl + r2 * W1 + xp);
        float a0 = 0.25f * v00 + 0.75f * v01, b0 = 0.75f * v01 + 0.25f * v02;
        float a1 = 0.25f * v10 + 0.75f * v11, b1 = 0.75f * v11 + 0.25f * v12;
        float a2 = 0.25f * v20 + 0.75f * v21, b2 = 0.75f * v21 + 0.25f * v22;
        float e0 = 0.25f * a0 + 0.75f * a1, o0 = 0.25f * b0 + 0.75f * b1;
        float e1 = 0.75f * a1 + 0.25f * a2, o1 = 0.75f * b1 + 0.25f * b2;
        int px = 2 * lane;
        tile[(0 * 64 + px)     * P1_PAD + cl] = __float2half_rn(e0);
        tile[(0 * 64 + px + 1) * P1_PAD + cl] = __float2half_rn(o0);
        tile[(1 * 64 + px)     * P1_PAD + cl] = __float2half_rn(e1);
        tile[(1 * 64 + px + 1) * P1_PAD + cl] = __float2half_rn(o1);
    }
    __syncthreads();
    for (int i = warp; i < 128; i += 8) {
        int row = i >> 6, px = i & 63;
        int xg = xb + px;
        if (xg < W0) {
            __half lo = tile[(row * 64 + px) * P1_PAD + 2 * lane];
            __half hi = tile[(row * 64 + px) * P1_PAD + 2 * lane + 1];
            *(__half2*)(gf + (size_t)((2 * Y + row) * W0 + xg) * C_TOT + 256 + cb + 2 * lane)
                = __halves2half2(lo, hi);
        }
    }
}

// ---------------------------------------------------------------------------
// prep2: 4x upsample feat2 -> channels [512,768). 64px tiles.
// ---------------------------------------------------------------------------
__global__ __launch_bounds__(256) void prep2_kernel(const float* __restrict__ f2) {
    __shared__ __half tile[2 * 64 * P2_PAD];
    int yb = blockIdx.y;
    int xb = blockIdx.x * 64;
    int cb = blockIdx.z * 64;
    int warp = threadIdx.x >> 5, lane = threadIdx.x & 31;
    __half* gf = (__half*)g_fused;
    int Y = yb >> 1, half = yb & 1;
    int ra = half ? Y : max(Y - 1, 0);
    int rb = half ? min(Y + 1, H2 - 1) : Y;
    float wya0, wyb0, wya1, wyb1;
    if (half == 0) { wya0 = 0.375f; wyb0 = 0.625f; wya1 = 0.125f; wyb1 = 0.875f; }
    else           { wya0 = 0.875f; wyb0 = 0.125f; wya1 = 0.625f; wyb1 = 0.375f; }
    if (lane < 16) {
        int j  = xb / 4 + lane;
        int xm = max(j - 1, 0), xc = min(j, W2 - 1), xp = min(j + 1, W2 - 1);
#pragma unroll
        for (int p = 0; p < 8; p++) {
            int cl = warp * 8 + p;
            const float* pl = f2 + (size_t)(cb + cl) * (H2 * W2);
            float va0 = __ldg(pl + ra * W2 + xm), va1 = __ldg(pl + ra * W2 + xc), va2 = __ldg(pl + ra * W2 + xp);
            float vb0 = __ldg(pl + rb * W2 + xm), vb1 = __ldg(pl + rb * W2 + xc), vb2 = __ldg(pl + rb * W2 + xp);
            float qa[4], qb[4];
            qa[0] = 0.375f * va0 + 0.625f * va1; qa[1] = 0.125f * va0 + 0.875f * va1;
            qa[2] = 0.875f * va1 + 0.125f * va2; qa[3] = 0.625f * va1 + 0.375f * va2;
            qb[0] = 0.375f * vb0 + 0.625f * vb1; qb[1] = 0.125f * vb0 + 0.875f * vb1;
            qb[2] = 0.875f * vb1 + 0.125f * vb2; qb[3] = 0.625f * vb1 + 0.375f * vb2;
            int px = 4 * lane;
#pragma unroll
            for (int q = 0; q < 4; q++) {
                float o0 = wya0 * qa[q] + wyb0 * qb[q];
                float o1 = wya1 * qa[q] + wyb1 * qb[q];
                tile[(0 * 64 + px + q) * P2_PAD + cl] = __float2half_rn(o0);
                tile[(1 * 64 + px + q) * P2_PAD + cl] = __float2half_rn(o1);
            }
        }
    }
    __syncthreads();
    int ybase = 4 * Y + 2 * half;
    for (int i = warp; i < 128; i += 8) {
        int row = i >> 6, px = i & 63;
        int xg = xb + px;
        if (xg < W0) {
            __half lo = tile[(row * 64 + px) * P2_PAD + 2 * lane];
            __half hi = tile[(row * 64 + px) * P2_PAD + 2 * lane + 1];
            *(__half2*)(gf + (size_t)((ybase + row) * W0 + xg) * C_TOT + 512 + cb + 2 * lane)
                = __halves2half2(lo, hi);
        }
    }
}

// ---------------------------------------------------------------------------
// RoIAlign over one 256-channel slab: grid (N), block 224 = 32 oct x 7 oh.
// Thread = (octet, oh), loops 7 ow: 112 independent LDG.128 taps (big ILP).
// Results staged in smem half [49][264], then the block's contiguous
// [256ch x 49] fp32 chunk is stored fully coalesced as float4.
// ---------------------------------------------------------------------------
#define OPP 96        // uint4 octets per pixel (full row)
#define SO_STRIDE 264 // padded row stride (halves) to spread smem banks

#define FMA8(t, kh, A) { \
    A[0] = __hfma2(kh, *(__half2*)&t.x, A[0]); \
    A[1] = __hfma2(kh, *(__half2*)&t.y, A[1]); \
    A[2] = __hfma2(kh, *(__half2*)&t.z, A[2]); \
    A[3] = __hfma2(kh, *(__half2*)&t.w, A[3]); }

__global__ __launch_bounds__(224) void roi_slab_kernel(
    const float* __restrict__ boxes,
    const int*   __restrict__ img_h,
    const int*   __restrict__ img_w,
    float* __restrict__ out,
    int slab)
{
    int roi = blockIdx.x;
    int tid = threadIdx.x;          // 0..223
    int octet = tid & 31;
    int oh    = tid >> 5;           // 0..6

    __shared__ int   sxo[14][2];
    __shared__ float swx[14][2];
    __shared__ int   syo[14][2];
    __shared__ float swy[14][2];    // scaled by 0.25
    __shared__ __half s_out[49 * SO_STRIDE];   // ~25.9KB

    if (tid < 56) {
        bool isx = tid < 28;
        int e = isx ? tid : tid - 28;
        int s = e >> 1, k = e & 1;      // sample 0..13, corner 0/1
        int bin = s >> 1, sub = s & 1;
        float offs = 0.25f + 0.5f * (float)sub;

        float scale = isx ? ((float)W0 / (float)__ldg(img_w))
                          : ((float)H0 / (float)__ldg(img_h));
        float p1 = __ldg(boxes + roi * 4 + (isx ? 0 : 1)) * scale;
        float p2 = __ldg(boxes + roi * 4 + (isx ? 2 : 3)) * scale;
        float bs = fmaxf(p2 - p1, 1.0f) * (1.0f / 7.0f);
        float P  = p1 + ((float)bin + offs) * bs;

        int lim = isx ? W0 : H0;
        bool valid = (P >= -1.0f) && (P <= (float)lim);
        float Pc = fminf(fmaxf(P, 0.0f), (float)(lim - 1));
        int c0  = (int)Pc;
        int c1  = min(c0 + 1, lim - 1);
        float l = Pc - (float)c0;
        float wv = valid ? (k ? l : 1.0f - l) : 0.0f;
        int corner = k ? c1 : c0;

        if (isx) {
            sxo[s][k] = corner * OPP;
            swx[s][k] = wv;
        } else {
            syo[s][k] = corner * (W0 * OPP);
            swy[s][k] = wv * 0.25f;
        }
    }
    __syncthreads();

    const uint4* fp = g_fused + slab * 32 + octet;

    int   ya0 = syo[2 * oh][0],     ya1 = syo[2 * oh][1];
    int   yb0 = syo[2 * oh + 1][0], yb1 = syo[2 * oh + 1][1];
    float wa0 = swy[2 * oh][0],     wa1 = swy[2 * oh][1];
    float wb0 = swy[2 * oh + 1][0], wb1 = swy[2 * oh + 1][1];

    const __half2 hz = __float2half2_rn(0.0f);

#pragma unroll
    for (int ow = 0; ow < 7; ow++) {
        int s0 = 2 * ow;
        int   x00 = sxo[s0][0],     x01 = sxo[s0][1];
        float u00 = swx[s0][0],     u01 = swx[s0][1];
        int   x10 = sxo[s0 + 1][0], x11 = sxo[s0 + 1][1];
        float u10 = swx[s0 + 1][0], u11 = swx[s0 + 1][1];

        __half2 A[4] = {hz, hz, hz, hz};
        __half2 B[4] = {hz, hz, hz, hz};

        // phase A: sub-sample 0 (x00/x01), 8 batched loads
        {
            __half2 k0 = __float2half2_rn(wa0 * u00);
            __half2 k1 = __float2half2_rn(wa1 * u00);
            __half2 k2 = __float2half2_rn(wb0 * u00);
            __half2 k3 = __float2half2_rn(wb1 * u00);
            __half2 k4 = __float2half2_rn(wa0 * u01);
            __half2 k5 = __float2half2_rn(wa1 * u01);
            __half2 k6 = __float2half2_rn(wb0 * u01);
            __half2 k7 = __float2half2_rn(wb1 * u01);
            uint4 t0 = __ldg(fp + ya0 + x00);
            uint4 t1 = __ldg(fp + ya1 + x00);
            uint4 t2 = __ldg(fp + yb0 + x00);
            uint4 t3 = __ldg(fp + yb1 + x00);
            uint4 t4 = __ldg(fp + ya0 + x01);
            uint4 t5 = __ldg(fp + ya1 + x01);
            uint4 t6 = __ldg(fp + yb0 + x01);
            uint4 t7 = __ldg(fp + yb1 + x01);
            FMA8(t0, k0, A) FMA8(t1, k1, A) FMA8(t2, k2, A) FMA8(t3, k3, A)
            FMA8(t4, k4, A) FMA8(t5, k5, A) FMA8(t6, k6, A) FMA8(t7, k7, A)
        }
        // phase B: sub-sample 1 (x10/x11), 8 batched loads
        {
            __half2 k0 = __float2half2_rn(wa0 * u10);
            __half2 k1 = __float2half2_rn(wa1 * u10);
            __half2 k2 = __float2half2_rn(wb0 * u10);
            __half2 k3 = __float2half2_rn(wb1 * u10);
            __half2 k4 = __float2half2_rn(wa0 * u11);
            __half2 k5 = __float2half2_rn(wa1 * u11);
            __half2 k6 = __float2half2_rn(wb0 * u11);
            __half2 k7 = __float2half2_rn(wb1 * u11);
            uint4 t0 = __ldg(fp + ya0 + x10);
            uint4 t1 = __ldg(fp + ya1 + x10);
            uint4 t2 = __ldg(fp + yb0 + x10);
            uint4 t3 = __ldg(fp + yb1 + x10);
            uint4 t4 = __ldg(fp + ya0 + x11);
            uint4 t5 = __ldg(fp + ya1 + x11);
            uint4 t6 = __ldg(fp + yb0 + x11);
            uint4 t7 = __ldg(fp + yb1 + x11);
            FMA8(t0, k0, B) FMA8(t1, k1, B) FMA8(t2, k2, B) FMA8(t3, k3, B)
            FMA8(t4, k4, B) FMA8(t5, k5, B) FMA8(t6, k6, B) FMA8(t7, k7, B)
        }

        __half2 c0 = __hadd2(A[0], B[0]);
        __half2 c1 = __hadd2(A[1], B[1]);
        __half2 c2 = __hadd2(A[2], B[2]);
        __half2 c3 = __hadd2(A[3], B[3]);
        uint4 st;
        st.x = *(unsigned*)&c0;  st.y = *(unsigned*)&c1;
        st.z = *(unsigned*)&c2;  st.w = *(unsigned*)&c3;
        *(uint4*)&s_out[(oh * 7 + ow) * SO_STRIDE + octet * 8] = st;
    }
    __syncthreads();

    // Coalesced store of the block's contiguous [256ch x 49] fp32 chunk.
    // chunk element e = c*49 + pos  <->  s_out[pos*SO_STRIDE + c]
    float* base = out + ((size_t)roi * C_TOT + slab * 256) * 49;
    int g = tid;                 // float4-group index, 3136 groups total
    int c = (4 * g) / 49;
    int r = (4 * g) % 49;
#pragma unroll
    for (int j = 0; j < 14; j++) {
        float4 v;
        int cc = c, rr = r;
        v.x = __half2float(s_out[rr * SO_STRIDE + cc]); if (++rr == 49) { rr = 0; cc++; }
        v.y = __half2float(s_out[rr * SO_STRIDE + cc]); if (++rr == 49) { rr = 0; cc++; }
        v.z = __half2float(s_out[rr * SO_STRIDE + cc]); if (++rr == 49) { rr = 0; cc++; }
        v.w = __half2float(s_out[rr * SO_STRIDE + cc]);
        *(float4*)(base + 4 * g) = v;
        g += 224;                        // +896 elements = 18*49 + 14
        c += 18; r += 14;
        if (r >= 49) { r -= 49; c++; }
    }
}

// ---------------------------------------------------------------------------
// Launch: 3 independent prep->roi chains on 3 streams (fork-join capture).
// ---------------------------------------------------------------------------
namespace {
struct Aux {
    cudaStream_t s1, s2;
    cudaEvent_t fork, j1, j2;
    Aux() {
        cudaStreamCreateWithFlags(&s1, cudaStreamNonBlocking);
        cudaStreamCreateWithFlags(&s2, cudaStreamNonBlocking);
        cudaEventCreateWithFlags(&fork, cudaEventDisableTiming);
        cudaEventCreateWithFlags(&j1, cudaEventDisableTiming);
        cudaEventCreateWithFlags(&j2, cudaEventDisableTiming);
    }
};
Aux& aux() { static Aux a; return a; }
}

extern "C" void kernel_launch(void* const* d_in, const int* in_sizes, int n_in,
                              void* d_out, int out_size) {
    const float* feat0 = (const float*)d_in[0];
    const float* feat1 = (const float*)d_in[1];
    const float* feat2 = (const float*)d_in[2];
    const float* boxes = (const float*)d_in[3];
    const int*   img_h = (const int*)d_in[4];
    const int*   img_w = (const int*)d_in[5];
    float* out = (float*)d_out;

    int N = in_sizes[3] / 4;
    Aux& a = aux();

    // fork from default (capture-origin) stream
    cudaEventRecord(a.fork, 0);
    cudaStreamWaitEvent(a.s1, a.fork, 0);
    cudaStreamWaitEvent(a.s2, a.fork, 0);

    // chain 0 on default stream
    prep0_kernel<<<dim3(10, 200, 4), 256>>>(feat0);
    roi_slab_kernel<<<N, 224>>>(boxes, img_h, img_w, out, 0);

    // chain 1 on s1
    prep1_kernel<<<dim3(5, 100, 4), 256, 0, a.s1>>>(feat1);
    roi_slab_kernel<<<N, 224, 0, a.s1>>>(boxes, img_h, img_w, out, 1);

    // chain 2 on s2
    prep2_kernel<<<dim3(5, 100, 4), 256, 0, a.s2>>>(feat2);
    roi_slab_kernel<<<N, 224, 0, a.s2>>>(boxes, img_h, img_w, out, 2);

    // join back to default stream
    cudaEventRecord(a.j1, a.s1);
    cudaEventRecord(a.j2, a.s2);
    cudaStreamWaitEvent(0, a.j1, 0);
    cudaStreamWaitEvent(0, a.j2, 0);
}